// round 10
// baseline (speedup 1.0000x reference)
#include <cuda_runtime.h>
#include <cuda_fp16.h>
#include <cstdint>

namespace {
constexpr int kNodes = 50000;
constexpr int kEdges = 500000;
constexpr int MM_SMEM = 50176;    // mm_kernel: sA 3*8K | sB 3*8K | bias 512B
// fq_kernel: sQ 16*4K=64K | sEf 4*4K=16K | stream 2*16K=32K  => 114688
constexpr int FQ_SMEM = 114688;
}

// ============================================================================
// Static scratch. All half matrices K-PERMUTED per 16-group:
//   kperm(k) = (k&~15) + ((k&7)>>1)*4 + (k&1) + ((k>>3)&1)*2
// ============================================================================
__device__ __half g_node_f[(size_t)kNodes * 128];
__device__ __half g_pab[(size_t)kNodes * 1024];   // [node_f@W1a + b1 | node_f@W1b]
__device__ __half g_xt[(size_t)kNodes * 128];
__device__ __half g_wnt[128 * 128];
__device__ __half g_wet[128 * 64];
__device__ __half g_w1ab[1024 * 128];
__device__ __half g_w1c[512 * 128];
__device__ __half g_w2t[256 * 512];
__device__ float  g_bias1024[1024];
__device__ int    g_src[kEdges];
__device__ int    g_dst[kEdges];
__device__ int    g_is64;

// ============================================================================
// Helpers
// ============================================================================
__device__ __forceinline__ void cp_async16(void* smem, const void* gmem) {
    uint32_t s;
    asm("{ .reg .u64 t; cvta.to.shared.u64 t, %1; cvt.u32.u64 %0, t; }" : "=r"(s) : "l"(smem));
    asm volatile("cp.async.cg.shared.global [%0], [%1], 16;\n" :: "r"(s), "l"(gmem));
}
__device__ __forceinline__ void cp_commit() { asm volatile("cp.async.commit_group;\n"); }
__device__ __forceinline__ void cp_wait0()  { asm volatile("cp.async.wait_group 0;\n" ::: "memory"); }
__device__ __forceinline__ void cp_wait1()  { asm volatile("cp.async.wait_group 1;\n" ::: "memory"); }

__device__ __forceinline__ void mma16816(float* cc, uint32_t a0, uint32_t a1,
                                         uint32_t a2, uint32_t a3,
                                         uint32_t b0, uint32_t b1) {
    asm volatile(
        "mma.sync.aligned.m16n8k16.row.col.f32.f16.f16.f32 "
        "{%0,%1,%2,%3}, {%4,%5,%6,%7}, {%8,%9}, {%0,%1,%2,%3};"
        : "+f"(cc[0]), "+f"(cc[1]), "+f"(cc[2]), "+f"(cc[3])
        : "r"(a0), "r"(a1), "r"(a2), "r"(a3), "r"(b0), "r"(b1));
}
__host__ __device__ __forceinline__ int kperm(int k) {
    return (k & ~15) + (((k & 7) >> 1) << 2) + (k & 1) + (((k >> 3) & 1) << 1);
}

// ============================================================================
// Prep kernels
// ============================================================================
__global__ void detect_idx_kernel(const void* idx) {
    if (threadIdx.x == 0 && blockIdx.x == 0) {
        const long long* p = (const long long*)idx;
        int ok = 1;
        for (int i = 0; i < 256; ++i) {
            long long v = p[i];
            if (v < 0 || v >= kNodes) { ok = 0; break; }
        }
        g_is64 = ok;
    }
}
__global__ void conv_idx_kernel(const void* idx) {
    int i = blockIdx.x * blockDim.x + threadIdx.x;
    if (i >= kEdges) return;
    int s, d;
    if (g_is64) {
        const long long* p = (const long long*)idx;
        s = (int)p[i]; d = (int)p[kEdges + i];
    } else {
        const int* p = (const int*)idx;
        s = p[i]; d = p[kEdges + i];
    }
    g_src[i] = s; g_dst[i] = d;
}

// All weight/activation preps fused into one launch (block-range dispatch):
//  [0,25000)      x -> g_xt (perm+round, C=128)
//  [25000,25064)  Wn -> g_wnt
//  [25064,25096)  We -> g_wet
//  [25096,25608)  W2 -> g_w2t
//  [25608,26120)  W1 rows 0..255 -> g_w1ab (a|b concat over N=1024)
//  [26120,26376)  W1 rows 256..383 -> g_w1c
//  [26376,26380)  b1 -> g_bias1024
__global__ void prep_kernel(const float* __restrict__ x,
                            const float* __restrict__ Wn, const float* __restrict__ We,
                            const float* __restrict__ W1, const float* __restrict__ W2,
                            const float* __restrict__ b1) {
    const int b = blockIdx.x;
    const int t = threadIdx.x;
    if (b < 25000) {
        int i = b * 256 + t;
        int row = i >> 7, k = i & 127;
        g_xt[(size_t)row * 128 + kperm(k)] = __float2half_rn(x[i]);
    } else if (b < 25064) {
        int i = (b - 25000) * 256 + t;       // i = k*128+n, K=128,N=128
        int k = i >> 7, n = i & 127;
        g_wnt[n * 128 + kperm(k)] = __float2half_rn(Wn[i]);
    } else if (b < 25096) {
        int i = (b - 25064) * 256 + t;       // K=64,N=128
        int k = i >> 7, n = i & 127;
        g_wet[n * 64 + kperm(k)] = __float2half_rn(We[i]);
    } else if (b < 25608) {
        int i = (b - 25096) * 256 + t;       // K=512,N=256
        int k = i >> 8, n = i & 255;
        g_w2t[(size_t)n * 512 + kperm(k)] = __float2half_rn(W2[i]);
    } else if (b < 26120) {
        int i = (b - 25608) * 256 + t;       // n = i>>7 (0..1023), k = i&127
        int n = i >> 7, k = i & 127;
        int srcRow = (n < 512) ? k : (128 + k);
        int srcCol = (n < 512) ? n : (n - 512);
        g_w1ab[(size_t)n * 128 + kperm(k)] = __float2half_rn(W1[(size_t)srcRow * 512 + srcCol]);
    } else if (b < 26376) {
        int i = (b - 26120) * 256 + t;       // n = i>>7 (0..511), k = i&127
        int n = i >> 7, k = i & 127;
        g_w1c[(size_t)n * 128 + kperm(k)] = __float2half_rn(W1[(size_t)(256 + k) * 512 + n]);
    } else {
        int i = (b - 26376) * 256 + t;
        if (i < 1024) g_bias1024[i] = (i < 512) ? b1[i] : 0.f;
    }
}

// ============================================================================
// FP16 mma GEMM (node-side): C[M,N] = act(A@Bt^T + bias), fp16 kperm store.
// ============================================================================
template <int K, int N, bool RELU>
__global__ __launch_bounds__(256, 2)
void mm_kernel(const __half* __restrict__ A, const __half* __restrict__ Bt,
               const float* __restrict__ bias, __half* __restrict__ Cmat, int M)
{
    constexpr int NS = K / 32;
    extern __shared__ char smc[];
    char*  sAc   = smc;
    char*  sBc   = smc + 24576;
    float* sBias = (float*)(smc + 49152);

    const int tid  = threadIdx.x;
    const int lane = tid & 31;
    const int warp = tid >> 5;
    const int r    = lane >> 2;
    const int c    = lane & 3;
    const int wm   = (warp >> 2) * 64;
    const int wnl  = (warp & 3) * 32;
    const int bn   = blockIdx.x * 128;
    const int bm   = blockIdx.y * 128;

    if (tid < 128) sBias[tid] = bias ? __ldg(bias + bn + tid) : 0.f;
    __syncthreads();

    auto load_stage = [&](int s) {
        const int buf = s % 3;
        const int k0 = s * 32;
        char* dA = sAc + buf * 8192;
        char* dB = sBc + buf * 8192;
#pragma unroll
        for (int t = 0; t < 2; ++t) {
            int idx = tid + t * 256;
            int row = idx >> 2, j = idx & 3;
            cp_async16(dA + row * 64 + ((j ^ (row & 3)) << 4),
                       A + (size_t)min(bm + row, M - 1) * K + k0 + j * 8);
        }
#pragma unroll
        for (int t = 0; t < 2; ++t) {
            int idx = tid + t * 256;
            int n = idx >> 2, j = idx & 3;
            cp_async16(dB + n * 64 + ((j ^ (n & 3)) << 4),
                       Bt + (size_t)(bn + n) * K + k0 + j * 8);
        }
    };

    float cf[4][4][4] = {};
    load_stage(0); cp_commit();
    if (NS > 1) { load_stage(1); cp_commit(); }

    for (int s = 0; s < NS; ++s) {
        if (s + 1 < NS) cp_wait1(); else cp_wait0();
        __syncthreads();
        if (s + 2 < NS) { load_stage(s + 2); cp_commit(); }

        const char* fA = sAc + (s % 3) * 8192;
        const char* fB = sBc + (s % 3) * 8192;
#pragma unroll
        for (int g = 0; g < 2; ++g) {
            const int coff = (((g * 2 + (c >> 1)) ^ (r & 3)) << 4) + (c & 1) * 8;
            uint2 ua[4], ub_[4], ubv[4];
#pragma unroll
            for (int ma = 0; ma < 4; ++ma) {
                const int row0 = wm + ma * 16 + r;
                ua[ma]  = *(const uint2*)(fA + row0 * 64 + coff);
                ub_[ma] = *(const uint2*)(fA + (row0 + 8) * 64 + coff);
            }
#pragma unroll
            for (int na = 0; na < 4; ++na)
                ubv[na] = *(const uint2*)(fB + (wnl + na * 8 + r) * 64 + coff);
#pragma unroll
            for (int ma = 0; ma < 4; ++ma)
#pragma unroll
                for (int na = 0; na < 4; ++na)
                    mma16816(cf[ma][na], ua[ma].x, ub_[ma].x, ua[ma].y, ub_[ma].y,
                             ubv[na].x, ubv[na].y);
        }
    }
    __syncthreads();

    float2 bias2[4];
#pragma unroll
    for (int na = 0; na < 4; ++na)
        bias2[na] = *(const float2*)&sBias[wnl + na * 8 + 2 * c];

#pragma unroll
    for (int ma = 0; ma < 4; ++ma) {
        const int row0 = bm + wm + ma * 16 + r;
        const int row1 = row0 + 8;
#pragma unroll
        for (int na = 0; na < 4; ++na) {
            const int nloc = wnl + na * 8 + 2 * c;
            const int pcol = bn + (nloc & ~15) + 4 * c + 2 * ((nloc >> 3) & 1);
            float v0 = cf[ma][na][0] + bias2[na].x;
            float v1 = cf[ma][na][1] + bias2[na].y;
            float v2 = cf[ma][na][2] + bias2[na].x;
            float v3 = cf[ma][na][3] + bias2[na].y;
            if (RELU) {
                v0 = fmaxf(v0, 0.f); v1 = fmaxf(v1, 0.f);
                v2 = fmaxf(v2, 0.f); v3 = fmaxf(v3, 0.f);
            }
            if (row0 < M) {
                __half2 h; h.x = __float2half_rn(v0); h.y = __float2half_rn(v1);
                *(__half2*)(Cmat + (size_t)row0 * N + pcol) = h;
            }
            if (row1 < M) {
                __half2 h; h.x = __float2half_rn(v2); h.y = __float2half_rn(v3);
                *(__half2*)(Cmat + (size_t)row1 * N + pcol) = h;
            }
        }
    }
}

// ============================================================================
// Fused edge kernel: per-CTA 64 edges, everything in smem.
//  P0: edge_f = relu(eattr@We+be)          -> sEf (4 stage-tiles, 16KB)
//  P1: Q = edge_f @ W1c                    -> sQ  (16 stage-tiles, 64KB)
//  P2: A = relu(Pa[src]+Pb[dst]+Q) in place; out = relu(A@W2+b2).W3 + b3
// Stage-tile layout (64 rows x 64B): addr = tile + row*64 + ((j^(row&3))<<4).
// Phase-2 Pa/Pb gathers are prefetched 2 K-stages ahead (double reg buffer).
// ============================================================================
__global__ __launch_bounds__(256, 2)
void fq_kernel(const float* __restrict__ eattr,
               const float* __restrict__ be, const float* __restrict__ b2,
               const float* __restrict__ W3, const float* __restrict__ b3,
               float* __restrict__ outv, int M)
{
    extern __shared__ char smc[];
    char* sQ  = smc;            // 16 x 4096
    char* sEf = smc + 65536;    // 4 x 4096
    char* sStr = smc + 81920;   // 32768 stream region

    const int tid  = threadIdx.x;
    const int lane = tid & 31;
    const int warp = tid >> 5;
    const int r    = lane >> 2;
    const int c    = lane & 3;
    const int bm   = blockIdx.x * 64;

    auto stsC = [&](char* tiles, int row, int nloc, float v0, float v1) {
        const int pcol = (nloc & ~15) + 4 * c + 2 * ((nloc >> 3) & 1);
        const int stage = pcol >> 5;
        const int byte = (pcol & 31) * 2;
        const int j = byte >> 4;
        __half2 h; h.x = __float2half_rn(v0); h.y = __float2half_rn(v1);
        *(__half2*)(tiles + stage * 4096 + row * 64 + ((j ^ (row & 3)) << 4) + (byte & 15)) = h;
    };

    // ================= Phase 0: edge encoder =================
    {
        char* sA0 = sStr;             // 2 x 4096
        char* sB0 = sStr + 8192;      // 2 x 8192
        float* sBe = (float*)(sStr + 24576);   // 128 f32

        if (tid < 128) sBe[tid] = __ldg(be + tid);
#pragma unroll
        for (int t = 0; t < 4; ++t) {
            int idx = tid + t * 256;
            int stage = idx >> 9, rem = idx & 511;
            int n = rem >> 2, j = rem & 3;
            cp_async16(sB0 + stage * 8192 + n * 64 + ((j ^ (n & 3)) << 4),
                       g_wet + (size_t)n * 64 + stage * 32 + j * 8);
        }
        cp_commit();
        {
            const int row = tid >> 2, seg = tid & 3;
            const int e = min(bm + row, M - 1);
            const float* es = eattr + (size_t)e * 64 + seg * 16;
            float ff[16];
#pragma unroll
            for (int q4 = 0; q4 < 4; ++q4) {
                float4 v = __ldg((const float4*)(es + q4 * 4));
                ff[q4 * 4] = v.x; ff[q4 * 4 + 1] = v.y;
                ff[q4 * 4 + 2] = v.z; ff[q4 * 4 + 3] = v.w;
            }
            __half arr[16];
#pragma unroll
            for (int kk = 0; kk < 16; ++kk) {
                int p = (((kk & 7) >> 1) << 2) + (kk & 1) + (((kk >> 3) & 1) << 1);
                arr[p] = __float2half_rn(ff[kk]);
            }
            const int stage = seg >> 1, jb = (seg & 1) * 2;
            char* base = sA0 + stage * 4096 + row * 64;
            *(uint4*)(base + (((jb    ) ^ (row & 3)) << 4)) = *(uint4*)arr;
            *(uint4*)(base + (((jb + 1) ^ (row & 3)) << 4)) = *(uint4*)(arr + 8);
        }
        cp_wait0();
        __syncthreads();

        const int wm0 = (warp >> 2) * 32;
        const int wnl0 = (warp & 3) * 32;
        float cf0[2][4][4] = {};
#pragma unroll
        for (int s0 = 0; s0 < 2; ++s0) {
            const char* fA = sA0 + s0 * 4096;
            const char* fB = sB0 + s0 * 8192;
#pragma unroll
            for (int g = 0; g < 2; ++g) {
                const int coff = (((g * 2 + (c >> 1)) ^ (r & 3)) << 4) + (c & 1) * 8;
                uint2 ua[2], ub_[2], ubv[4];
#pragma unroll
                for (int ma = 0; ma < 2; ++ma) {
                    const int row0 = wm0 + ma * 16 + r;
                    ua[ma]  = *(const uint2*)(fA + row0 * 64 + coff);
                    ub_[ma] = *(const uint2*)(fA + (row0 + 8) * 64 + coff);
                }
#pragma unroll
                for (int na = 0; na < 4; ++na)
                    ubv[na] = *(const uint2*)(fB + (wnl0 + na * 8 + r) * 64 + coff);
#pragma unroll
                for (int ma = 0; ma < 2; ++ma)
#pragma unroll
                    for (int na = 0; na < 4; ++na)
                        mma16816(cf0[ma][na], ua[ma].x, ub_[ma].x, ua[ma].y, ub_[ma].y,
                                 ubv[na].x, ubv[na].y);
            }
        }
        __syncthreads();
#pragma unroll
        for (int ma = 0; ma < 2; ++ma) {
            const int row0 = wm0 + ma * 16 + r;
#pragma unroll
            for (int na = 0; na < 4; ++na) {
                const int nloc = wnl0 + na * 8 + 2 * c;
                float b0 = sBe[nloc], b1v = sBe[nloc + 1];
                stsC(sEf, row0,     nloc, fmaxf(cf0[ma][na][0] + b0, 0.f),
                                          fmaxf(cf0[ma][na][1] + b1v, 0.f));
                stsC(sEf, row0 + 8, nloc, fmaxf(cf0[ma][na][2] + b0, 0.f),
                                          fmaxf(cf0[ma][na][3] + b1v, 0.f));
            }
        }
        __syncthreads();
    }

    // ================= Phase 1: Q = edge_f @ W1c (2 passes of N=256) ========
    {
        const int wnl = warp * 32;
        auto cpB1 = [&](int np, int s) {
            char* dB = sStr + (s & 1) * 16384;
#pragma unroll
            for (int t = 0; t < 4; ++t) {
                int idx = tid + t * 256;
                int n = idx >> 2, j = idx & 3;
                cp_async16(dB + n * 64 + ((j ^ (n & 3)) << 4),
                           g_w1c + (size_t)(np * 256 + n) * 128 + s * 32 + j * 8);
            }
        };
#pragma unroll
        for (int np = 0; np < 2; ++np) {
            float cf1[4][4][4] = {};
            cpB1(np, 0); cp_commit();
            cpB1(np, 1); cp_commit();
#pragma unroll
            for (int s = 0; s < 4; ++s) {
                if (s + 1 < 4) cp_wait1(); else cp_wait0();
                __syncthreads();
                const char* fA = sEf + s * 4096;
                const char* fB = sStr + (s & 1) * 16384;
#pragma unroll
                for (int g = 0; g < 2; ++g) {
                    const int coff = (((g * 2 + (c >> 1)) ^ (r & 3)) << 4) + (c & 1) * 8;
                    uint2 ua[4], ub_[4], ubv[4];
#pragma unroll
                    for (int ma = 0; ma < 4; ++ma) {
                        const int row0 = ma * 16 + r;
                        ua[ma]  = *(const uint2*)(fA + row0 * 64 + coff);
                        ub_[ma] = *(const uint2*)(fA + (row0 + 8) * 64 + coff);
                    }
#pragma unroll
                    for (int na = 0; na < 4; ++na)
                        ubv[na] = *(const uint2*)(fB + (wnl + na * 8 + r) * 64 + coff);
#pragma unroll
                    for (int ma = 0; ma < 4; ++ma)
#pragma unroll
                        for (int na = 0; na < 4; ++na)
                            mma16816(cf1[ma][na], ua[ma].x, ub_[ma].x, ua[ma].y, ub_[ma].y,
                                     ubv[na].x, ubv[na].y);
                }
                __syncthreads();
                if (s + 2 < 4) { cpB1(np, s + 2); cp_commit(); }
            }
#pragma unroll
            for (int ma = 0; ma < 4; ++ma) {
                const int row0 = ma * 16 + r;
#pragma unroll
                for (int na = 0; na < 4; ++na) {
                    const int nloc = np * 256 + wnl + na * 8 + 2 * c;
                    stsC(sQ, row0,     nloc, cf1[ma][na][0], cf1[ma][na][1]);
                    stsC(sQ, row0 + 8, nloc, cf1[ma][na][2], cf1[ma][na][3]);
                }
            }
            __syncthreads();
        }
    }

    // ================= Phase 2: W2 + W3 =================
    {
        float* sB2 = (float*)sEf;            // 256 f32
        float* sW3 = (float*)(sEf + 1024);   // 256 f32
        float* psum = (float*)(sEf + 2048);  // 64 x 8 f32
        sB2[tid] = __ldg(b2 + tid);
        sW3[tid] = __ldg(W3 + tid);

        const int row = tid >> 2, j = tid & 3;
        const int e = min(bm + row, M - 1);
        const __half* paP = g_pab + (size_t)g_src[e] * 1024;
        const __half* pbP = g_pab + (size_t)g_dst[e] * 1024 + 512;
        char* qaddrBase = sQ + row * 64 + ((j ^ (row & 3)) << 4);

        uint4 ra[2], rb[2];
        auto ldgA = [&](int s, int slot) {
            ra[slot] = __ldg((const uint4*)(paP + s * 32 + j * 8));
            rb[slot] = __ldg((const uint4*)(pbP + s * 32 + j * 8));
        };
        auto finA = [&](int s, int slot) {
            uint4 q4 = *(uint4*)(qaddrBase + s * 4096);
            const half2* qh = (const half2*)&q4;
            const half2* ha = (const half2*)&ra[slot];
            const half2* hb = (const half2*)&rb[slot];
            half2 v[4];
            const half2 z = __float2half2_rn(0.f);
#pragma unroll
            for (int i = 0; i < 4; ++i)
                v[i] = __hmax2(__hadd2(__hadd2(qh[i], ha[i]), hb[i]), z);
            *(uint4*)(qaddrBase + s * 4096) = *(uint4*)v;
        };
        auto cpB2 = [&](int s) {
            char* dB = sStr + (s & 1) * 16384;
#pragma unroll
            for (int t = 0; t < 4; ++t) {
                int idx = tid + t * 256;
                int n = idx >> 2, j2 = idx & 3;
                cp_async16(dB + n * 64 + ((j2 ^ (n & 3)) << 4),
                           g_w2t + (size_t)n * 512 + s * 32 + j2 * 8);
            }
        };

        const int wnl = warp * 32;
        float cf[4][4][4] = {};

        ldgA(0, 0); ldgA(1, 1);
        cpB2(0); cp_commit();
        cpB2(1); cp_commit();

#pragma unroll 1
        for (int s = 0; s < 16; ++s) {
            finA(s, s & 1);
            if (s + 2 < 16) ldgA(s + 2, s & 1);
            if (s + 1 < 16) cp_wait1(); else cp_wait0();
            __syncthreads();
            const char* fA = sQ + s * 4096;
            const char* fB = sStr + (s & 1) * 16384;
#pragma unroll
            for (int g = 0; g < 2; ++g) {
                const int coff = (((g * 2 + (c >> 1)) ^ (r & 3)) << 4) + (c & 1) * 8;
                uint2 ua[4], ub_[4], ubv[4];
#pragma unroll
                for (int ma = 0; ma < 4; ++ma) {
                    const int row0 = ma * 16 + r;
                    ua[ma]  = *(const uint2*)(fA + row0 * 64 + coff);
                    ub_[ma] = *(const uint2*)(fA + (row0 + 8) * 64 + coff);
                }
#pragma unroll
                for (int na = 0; na < 4; ++na)
                    ubv[na] = *(const uint2*)(fB + (wnl + na * 8 + r) * 64 + coff);
#pragma unroll
                for (int ma = 0; ma < 4; ++ma)
#pragma unroll
                    for (int na = 0; na < 4; ++na)
                        mma16816(cf[ma][na], ua[ma].x, ub_[ma].x, ua[ma].y, ub_[ma].y,
                                 ubv[na].x, ubv[na].y);
            }
            __syncthreads();
            if (s + 2 < 16) { cpB2(s + 2); cp_commit(); }
        }

        float2 bias2[4], w3v[4];
#pragma unroll
        for (int na = 0; na < 4; ++na) {
            bias2[na] = *(const float2*)&sB2[wnl + na * 8 + 2 * c];
            w3v[na]   = *(const float2*)&sW3[wnl + na * 8 + 2 * c];
        }
#pragma unroll
        for (int ma = 0; ma < 4; ++ma) {
            float p0 = 0.f, p1 = 0.f;
#pragma unroll
            for (int na = 0; na < 4; ++na) {
                p0 += fmaxf(cf[ma][na][0] + bias2[na].x, 0.f) * w3v[na].x
                    + fmaxf(cf[ma][na][1] + bias2[na].y, 0.f) * w3v[na].y;
                p1 += fmaxf(cf[ma][na][2] + bias2[na].x, 0.f) * w3v[na].x
                    + fmaxf(cf[ma][na][3] + bias2[na].y, 0.f) * w3v[na].y;
            }
            p0 += __shfl_xor_sync(0xffffffffu, p0, 1);
            p0 += __shfl_xor_sync(0xffffffffu, p0, 2);
            p1 += __shfl_xor_sync(0xffffffffu, p1, 1);
            p1 += __shfl_xor_sync(0xffffffffu, p1, 2);
            if (c == 0) {
                const int rl = ma * 16 + r;
                psum[rl * 8 + warp] = p0;
                psum[(rl + 8) * 8 + warp] = p1;
            }
        }
        __syncthreads();
        if (tid < 64) {
            const int gm = bm + tid;
            if (gm < M) {
                float s = 0.f;
#pragma unroll
                for (int w = 0; w < 8; ++w) s += psum[tid * 8 + w];
                outv[gm] = s + __ldg(b3);
            }
        }
    }
}

// ============================================================================
extern "C" void kernel_launch(void* const* d_in, const int* in_sizes, int n_in,
                              void* d_out, int out_size)
{
    const float* x     = (const float*)d_in[0];
    const void*  eidx  = d_in[1];
    const float* eattr = (const float*)d_in[2];
    const float* Wn    = (const float*)d_in[3];
    const float* bnode = (const float*)d_in[4];
    const float* We    = (const float*)d_in[5];
    const float* be    = (const float*)d_in[6];
    const float* W1    = (const float*)d_in[7];
    const float* b1    = (const float*)d_in[8];
    const float* W2    = (const float*)d_in[9];
    const float* b2    = (const float*)d_in[10];
    const float* W3    = (const float*)d_in[11];
    const float* b3    = (const float*)d_in[12];
    float* out = (float*)d_out;

    __half *p_node, *p_pab, *p_xt, *p_wnt, *p_w1ab;
    float* p_b1024;
    cudaGetSymbolAddress((void**)&p_node, g_node_f);
    cudaGetSymbolAddress((void**)&p_pab, g_pab);
    cudaGetSymbolAddress((void**)&p_xt, g_xt);
    cudaGetSymbolAddress((void**)&p_wnt, g_wnt);
    cudaGetSymbolAddress((void**)&p_w1ab, g_w1ab);
    cudaGetSymbolAddress((void**)&p_b1024, g_bias1024);

    // launches: 0 detect, 1 conv, 2 prep, 3 node_enc, 4 pab, 5 fq  (ncu -s5 -> fq)
    detect_idx_kernel<<<1, 32>>>(eidx);
    conv_idx_kernel<<<(kEdges + 255) / 256, 256>>>(eidx);
    prep_kernel<<<26380, 256>>>(x, Wn, We, W1, W2, b1);

    // node encoder [50000,128]
    cudaFuncSetAttribute(mm_kernel<128, 128, true>,
                         cudaFuncAttributeMaxDynamicSharedMemorySize, MM_SMEM);
    mm_kernel<128, 128, true><<<dim3(1, (kNodes + 127) / 128), 256, MM_SMEM>>>(
        p_xt, p_wnt, bnode, p_node, kNodes);

    // Pab = node_f @ [W1a|W1b] + [b1|0]   [50000,1024]
    cudaFuncSetAttribute(mm_kernel<128, 1024, false>,
                         cudaFuncAttributeMaxDynamicSharedMemorySize, MM_SMEM);
    mm_kernel<128, 1024, false><<<dim3(8, (kNodes + 127) / 128), 256, MM_SMEM>>>(
        p_node, p_w1ab, p_b1024, p_pab, kNodes);

    // fused edge pipeline
    cudaFuncSetAttribute(fq_kernel,
                         cudaFuncAttributeMaxDynamicSharedMemorySize, FQ_SMEM);
    fq_kernel<<<(kEdges + 63) / 64, 256, FQ_SMEM>>>(eattr, be, b2, W3, b3, out, kEdges);
}

// round 11
// speedup vs baseline: 1.2097x; 1.2097x over previous
#include <cuda_runtime.h>
#include <cuda_fp16.h>
#include <cstdint>

namespace {
constexpr int kNodes = 50000;
constexpr int kEdges = 500000;
constexpr int MM_SMEM = 50176;    // mm_kernel: sA 3*8K | sB 3*8K | bias 512B
// fq_kernel: sQ 16*4K=64K | sEf 4*4K=16K | stream 2*16K=32K  => 114688
constexpr int FQ_SMEM = 114688;
}

// ============================================================================
// Static scratch. All half matrices K-PERMUTED per 16-group:
//   kperm(k) = (k&~15) + ((k&7)>>1)*4 + (k&1) + ((k>>3)&1)*2
// ============================================================================
__device__ __half g_node_f[(size_t)kNodes * 128];
__device__ __half g_pab[(size_t)kNodes * 1024];   // [node_f@W1a + b1 | node_f@W1b]
__device__ __half g_xt[(size_t)kNodes * 128];
__device__ __half g_wnt[128 * 128];
__device__ __half g_wet[128 * 64];
__device__ __half g_w1ab[1024 * 128];
__device__ __half g_w1c[512 * 128];
__device__ __half g_w2t[256 * 512];
__device__ float  g_bias1024[1024];
__device__ int    g_src[kEdges];
__device__ int    g_dst[kEdges];
__device__ int    g_is64;

// ============================================================================
// Helpers
// ============================================================================
__device__ __forceinline__ void cp_async16(void* smem, const void* gmem) {
    uint32_t s;
    asm("{ .reg .u64 t; cvta.to.shared.u64 t, %1; cvt.u32.u64 %0, t; }" : "=r"(s) : "l"(smem));
    asm volatile("cp.async.cg.shared.global [%0], [%1], 16;\n" :: "r"(s), "l"(gmem));
}
__device__ __forceinline__ void cp_commit() { asm volatile("cp.async.commit_group;\n"); }
__device__ __forceinline__ void cp_wait0()  { asm volatile("cp.async.wait_group 0;\n" ::: "memory"); }
__device__ __forceinline__ void cp_wait1()  { asm volatile("cp.async.wait_group 1;\n" ::: "memory"); }

__device__ __forceinline__ void mma16816(float* cc, uint32_t a0, uint32_t a1,
                                         uint32_t a2, uint32_t a3,
                                         uint32_t b0, uint32_t b1) {
    asm volatile(
        "mma.sync.aligned.m16n8k16.row.col.f32.f16.f16.f32 "
        "{%0,%1,%2,%3}, {%4,%5,%6,%7}, {%8,%9}, {%0,%1,%2,%3};"
        : "+f"(cc[0]), "+f"(cc[1]), "+f"(cc[2]), "+f"(cc[3])
        : "r"(a0), "r"(a1), "r"(a2), "r"(a3), "r"(b0), "r"(b1));
}
__host__ __device__ __forceinline__ int kperm(int k) {
    return (k & ~15) + (((k & 7) >> 1) << 2) + (k & 1) + (((k >> 3) & 1) << 1);
}

// ============================================================================
// Index prep
// ============================================================================
__global__ void detect_idx_kernel(const void* idx) {
    if (threadIdx.x == 0 && blockIdx.x == 0) {
        const long long* p = (const long long*)idx;
        int ok = 1;
        for (int i = 0; i < 256; ++i) {
            long long v = p[i];
            if (v < 0 || v >= kNodes) { ok = 0; break; }
        }
        g_is64 = ok;
    }
}
__global__ void conv_idx_kernel(const void* idx) {
    int i = blockIdx.x * blockDim.x + threadIdx.x;
    if (i >= kEdges) return;
    int s, d;
    if (g_is64) {
        const long long* p = (const long long*)idx;
        s = (int)p[i]; d = (int)p[kEdges + i];
    } else {
        const int* p = (const int*)idx;
        s = p[i]; d = p[kEdges + i];
    }
    g_src[i] = s; g_dst[i] = d;
}

// All weight/activation preps in one launch (block-range dispatch).
// x path vectorized: kperm maps pairs (2k,2k+1) to adjacent positions,
// so one float2 load -> one half2 store.
//  [0,12500)      x -> g_xt        (2 elems/thread)
//  [12500,12564)  Wn -> g_wnt
//  [12564,12596)  We -> g_wet
//  [12596,13108)  W2 -> g_w2t
//  [13108,13620)  W1 rows 0..255 -> g_w1ab
//  [13620,13876)  W1 rows 256..383 -> g_w1c
//  [13876,13880)  b1 -> g_bias1024
__global__ void prep_kernel(const float* __restrict__ x,
                            const float* __restrict__ Wn, const float* __restrict__ We,
                            const float* __restrict__ W1, const float* __restrict__ W2,
                            const float* __restrict__ b1) {
    const int b = blockIdx.x;
    const int t = threadIdx.x;
    if (b < 12500) {
        int i2 = b * 256 + t;                // pair index
        int row = i2 >> 6, kp = (i2 & 63) * 2;
        float2 v = *(const float2*)(x + (size_t)row * 128 + kp);
        __half2 h; h.x = __float2half_rn(v.x); h.y = __float2half_rn(v.y);
        *(__half2*)(g_xt + (size_t)row * 128 + kperm(kp)) = h;
    } else if (b < 12564) {
        int i = (b - 12500) * 256 + t;       // K=128,N=128
        int k = i >> 7, n = i & 127;
        g_wnt[n * 128 + kperm(k)] = __float2half_rn(Wn[i]);
    } else if (b < 12596) {
        int i = (b - 12564) * 256 + t;       // K=64,N=128
        int k = i >> 7, n = i & 127;
        g_wet[n * 64 + kperm(k)] = __float2half_rn(We[i]);
    } else if (b < 13108) {
        int i = (b - 12596) * 256 + t;       // K=512,N=256
        int k = i >> 8, n = i & 255;
        g_w2t[(size_t)n * 512 + kperm(k)] = __float2half_rn(W2[i]);
    } else if (b < 13620) {
        int i = (b - 13108) * 256 + t;       // n = i>>7 (0..1023), k = i&127
        int n = i >> 7, k = i & 127;
        int srcRow = (n < 512) ? k : (128 + k);
        int srcCol = (n < 512) ? n : (n - 512);
        g_w1ab[(size_t)n * 128 + kperm(k)] = __float2half_rn(W1[(size_t)srcRow * 512 + srcCol]);
    } else if (b < 13876) {
        int i = (b - 13620) * 256 + t;       // n = i>>7 (0..511), k = i&127
        int n = i >> 7, k = i & 127;
        g_w1c[(size_t)n * 128 + kperm(k)] = __float2half_rn(W1[(size_t)(256 + k) * 512 + n]);
    } else {
        int i = (b - 13876) * 256 + t;
        if (i < 1024) g_bias1024[i] = (i < 512) ? b1[i] : 0.f;
    }
}

// ============================================================================
// FP16 mma GEMM (node-side): C[M,N] = act(A@Bt^T + bias), fp16 kperm store.
// ============================================================================
template <int K, int N, bool RELU>
__global__ __launch_bounds__(256, 2)
void mm_kernel(const __half* __restrict__ A, const __half* __restrict__ Bt,
               const float* __restrict__ bias, __half* __restrict__ Cmat, int M)
{
    constexpr int NS = K / 32;
    extern __shared__ char smc[];
    char*  sAc   = smc;
    char*  sBc   = smc + 24576;
    float* sBias = (float*)(smc + 49152);

    const int tid  = threadIdx.x;
    const int lane = tid & 31;
    const int warp = tid >> 5;
    const int r    = lane >> 2;
    const int c    = lane & 3;
    const int wm   = (warp >> 2) * 64;
    const int wnl  = (warp & 3) * 32;
    const int bn   = blockIdx.x * 128;
    const int bm   = blockIdx.y * 128;

    if (tid < 128) sBias[tid] = bias ? __ldg(bias + bn + tid) : 0.f;
    __syncthreads();

    auto load_stage = [&](int s) {
        const int buf = s % 3;
        const int k0 = s * 32;
        char* dA = sAc + buf * 8192;
        char* dB = sBc + buf * 8192;
#pragma unroll
        for (int t = 0; t < 2; ++t) {
            int idx = tid + t * 256;
            int row = idx >> 2, j = idx & 3;
            cp_async16(dA + row * 64 + ((j ^ (row & 3)) << 4),
                       A + (size_t)min(bm + row, M - 1) * K + k0 + j * 8);
        }
#pragma unroll
        for (int t = 0; t < 2; ++t) {
            int idx = tid + t * 256;
            int n = idx >> 2, j = idx & 3;
            cp_async16(dB + n * 64 + ((j ^ (n & 3)) << 4),
                       Bt + (size_t)(bn + n) * K + k0 + j * 8);
        }
    };

    float cf[4][4][4] = {};
    load_stage(0); cp_commit();
    if (NS > 1) { load_stage(1); cp_commit(); }

    for (int s = 0; s < NS; ++s) {
        if (s + 1 < NS) cp_wait1(); else cp_wait0();
        __syncthreads();
        if (s + 2 < NS) { load_stage(s + 2); cp_commit(); }

        const char* fA = sAc + (s % 3) * 8192;
        const char* fB = sBc + (s % 3) * 8192;
#pragma unroll
        for (int g = 0; g < 2; ++g) {
            const int coff = (((g * 2 + (c >> 1)) ^ (r & 3)) << 4) + (c & 1) * 8;
            uint2 ua[4], ub_[4], ubv[4];
#pragma unroll
            for (int ma = 0; ma < 4; ++ma) {
                const int row0 = wm + ma * 16 + r;
                ua[ma]  = *(const uint2*)(fA + row0 * 64 + coff);
                ub_[ma] = *(const uint2*)(fA + (row0 + 8) * 64 + coff);
            }
#pragma unroll
            for (int na = 0; na < 4; ++na)
                ubv[na] = *(const uint2*)(fB + (wnl + na * 8 + r) * 64 + coff);
#pragma unroll
            for (int ma = 0; ma < 4; ++ma)
#pragma unroll
                for (int na = 0; na < 4; ++na)
                    mma16816(cf[ma][na], ua[ma].x, ub_[ma].x, ua[ma].y, ub_[ma].y,
                             ubv[na].x, ubv[na].y);
        }
    }
    __syncthreads();

    float2 bias2[4];
#pragma unroll
    for (int na = 0; na < 4; ++na)
        bias2[na] = *(const float2*)&sBias[wnl + na * 8 + 2 * c];

#pragma unroll
    for (int ma = 0; ma < 4; ++ma) {
        const int row0 = bm + wm + ma * 16 + r;
        const int row1 = row0 + 8;
#pragma unroll
        for (int na = 0; na < 4; ++na) {
            const int nloc = wnl + na * 8 + 2 * c;
            const int pcol = bn + (nloc & ~15) + 4 * c + 2 * ((nloc >> 3) & 1);
            float v0 = cf[ma][na][0] + bias2[na].x;
            float v1 = cf[ma][na][1] + bias2[na].y;
            float v2 = cf[ma][na][2] + bias2[na].x;
            float v3 = cf[ma][na][3] + bias2[na].y;
            if (RELU) {
                v0 = fmaxf(v0, 0.f); v1 = fmaxf(v1, 0.f);
                v2 = fmaxf(v2, 0.f); v3 = fmaxf(v3, 0.f);
            }
            if (row0 < M) {
                __half2 h; h.x = __float2half_rn(v0); h.y = __float2half_rn(v1);
                *(__half2*)(Cmat + (size_t)row0 * N + pcol) = h;
            }
            if (row1 < M) {
                __half2 h; h.x = __float2half_rn(v2); h.y = __float2half_rn(v3);
                *(__half2*)(Cmat + (size_t)row1 * N + pcol) = h;
            }
        }
    }
}

// ============================================================================
// Fused edge kernel: per-CTA 64 edges, everything in smem.
//  P0: edge_f = relu(eattr@We+be)          -> sEf (4 stage-tiles, 16KB)
//  P1: Q = edge_f @ W1c                    -> sQ  (16 stage-tiles, 64KB)
//  P2: A = relu(Pa[src]+Pb[dst]+Q) in place; out = relu(A@W2+b2).W3 + b3
// Stage-tile layout (64 rows x 64B): addr = tile + row*64 + ((j^(row&3))<<4).
// Phase-2 Pa/Pb gather prefetch is SINGLE-depth (register budget: 128/thread).
// ============================================================================
__global__ __launch_bounds__(256, 2)
void fq_kernel(const float* __restrict__ eattr,
               const float* __restrict__ be, const float* __restrict__ b2,
               const float* __restrict__ W3, const float* __restrict__ b3,
               float* __restrict__ outv, int M)
{
    extern __shared__ char smc[];
    char* sQ  = smc;            // 16 x 4096
    char* sEf = smc + 65536;    // 4 x 4096
    char* sStr = smc + 81920;   // 32768 stream region

    const int tid  = threadIdx.x;
    const int lane = tid & 31;
    const int warp = tid >> 5;
    const int r    = lane >> 2;
    const int c    = lane & 3;
    const int bm   = blockIdx.x * 64;

    auto stsC = [&](char* tiles, int row, int nloc, float v0, float v1) {
        const int pcol = (nloc & ~15) + 4 * c + 2 * ((nloc >> 3) & 1);
        const int stage = pcol >> 5;
        const int byte = (pcol & 31) * 2;
        const int j = byte >> 4;
        __half2 h; h.x = __float2half_rn(v0); h.y = __float2half_rn(v1);
        *(__half2*)(tiles + stage * 4096 + row * 64 + ((j ^ (row & 3)) << 4) + (byte & 15)) = h;
    };

    // ================= Phase 0: edge encoder =================
    {
        char* sA0 = sStr;             // 2 x 4096
        char* sB0 = sStr + 8192;      // 2 x 8192
        float* sBe = (float*)(sStr + 24576);   // 128 f32

        if (tid < 128) sBe[tid] = __ldg(be + tid);
#pragma unroll
        for (int t = 0; t < 4; ++t) {
            int idx = tid + t * 256;
            int stage = idx >> 9, rem = idx & 511;
            int n = rem >> 2, j = rem & 3;
            cp_async16(sB0 + stage * 8192 + n * 64 + ((j ^ (n & 3)) << 4),
                       g_wet + (size_t)n * 64 + stage * 32 + j * 8);
        }
        cp_commit();
        {
            const int row = tid >> 2, seg = tid & 3;
            const int e = min(bm + row, M - 1);
            const float* es = eattr + (size_t)e * 64 + seg * 16;
            float ff[16];
#pragma unroll
            for (int q4 = 0; q4 < 4; ++q4) {
                float4 v = __ldg((const float4*)(es + q4 * 4));
                ff[q4 * 4] = v.x; ff[q4 * 4 + 1] = v.y;
                ff[q4 * 4 + 2] = v.z; ff[q4 * 4 + 3] = v.w;
            }
            __half arr[16];
#pragma unroll
            for (int kk = 0; kk < 16; ++kk) {
                int p = (((kk & 7) >> 1) << 2) + (kk & 1) + (((kk >> 3) & 1) << 1);
                arr[p] = __float2half_rn(ff[kk]);
            }
            const int stage = seg >> 1, jb = (seg & 1) * 2;
            char* base = sA0 + stage * 4096 + row * 64;
            *(uint4*)(base + (((jb    ) ^ (row & 3)) << 4)) = *(uint4*)arr;
            *(uint4*)(base + (((jb + 1) ^ (row & 3)) << 4)) = *(uint4*)(arr + 8);
        }
        cp_wait0();
        __syncthreads();

        const int wm0 = (warp >> 2) * 32;
        const int wnl0 = (warp & 3) * 32;
        float cf0[2][4][4] = {};
#pragma unroll
        for (int s0 = 0; s0 < 2; ++s0) {
            const char* fA = sA0 + s0 * 4096;
            const char* fB = sB0 + s0 * 8192;
#pragma unroll
            for (int g = 0; g < 2; ++g) {
                const int coff = (((g * 2 + (c >> 1)) ^ (r & 3)) << 4) + (c & 1) * 8;
                uint2 ua[2], ub_[2], ubv[4];
#pragma unroll
                for (int ma = 0; ma < 2; ++ma) {
                    const int row0 = wm0 + ma * 16 + r;
                    ua[ma]  = *(const uint2*)(fA + row0 * 64 + coff);
                    ub_[ma] = *(const uint2*)(fA + (row0 + 8) * 64 + coff);
                }
#pragma unroll
                for (int na = 0; na < 4; ++na)
                    ubv[na] = *(const uint2*)(fB + (wnl0 + na * 8 + r) * 64 + coff);
#pragma unroll
                for (int ma = 0; ma < 2; ++ma)
#pragma unroll
                    for (int na = 0; na < 4; ++na)
                        mma16816(cf0[ma][na], ua[ma].x, ub_[ma].x, ua[ma].y, ub_[ma].y,
                                 ubv[na].x, ubv[na].y);
            }
        }
        __syncthreads();
#pragma unroll
        for (int ma = 0; ma < 2; ++ma) {
            const int row0 = wm0 + ma * 16 + r;
#pragma unroll
            for (int na = 0; na < 4; ++na) {
                const int nloc = wnl0 + na * 8 + 2 * c;
                float b0 = sBe[nloc], b1v = sBe[nloc + 1];
                stsC(sEf, row0,     nloc, fmaxf(cf0[ma][na][0] + b0, 0.f),
                                          fmaxf(cf0[ma][na][1] + b1v, 0.f));
                stsC(sEf, row0 + 8, nloc, fmaxf(cf0[ma][na][2] + b0, 0.f),
                                          fmaxf(cf0[ma][na][3] + b1v, 0.f));
            }
        }
        __syncthreads();
    }

    // ================= Phase 1: Q = edge_f @ W1c (2 passes of N=256) ========
    {
        const int wnl = warp * 32;
        auto cpB1 = [&](int np, int s) {
            char* dB = sStr + (s & 1) * 16384;
#pragma unroll
            for (int t = 0; t < 4; ++t) {
                int idx = tid + t * 256;
                int n = idx >> 2, j = idx & 3;
                cp_async16(dB + n * 64 + ((j ^ (n & 3)) << 4),
                           g_w1c + (size_t)(np * 256 + n) * 128 + s * 32 + j * 8);
            }
        };
#pragma unroll
        for (int np = 0; np < 2; ++np) {
            float cf1[4][4][4] = {};
            cpB1(np, 0); cp_commit();
            cpB1(np, 1); cp_commit();
#pragma unroll
            for (int s = 0; s < 4; ++s) {
                if (s + 1 < 4) cp_wait1(); else cp_wait0();
                __syncthreads();
                const char* fA = sEf + s * 4096;
                const char* fB = sStr + (s & 1) * 16384;
#pragma unroll
                for (int g = 0; g < 2; ++g) {
                    const int coff = (((g * 2 + (c >> 1)) ^ (r & 3)) << 4) + (c & 1) * 8;
                    uint2 ua[4], ub_[4], ubv[4];
#pragma unroll
                    for (int ma = 0; ma < 4; ++ma) {
                        const int row0 = ma * 16 + r;
                        ua[ma]  = *(const uint2*)(fA + row0 * 64 + coff);
                        ub_[ma] = *(const uint2*)(fA + (row0 + 8) * 64 + coff);
                    }
#pragma unroll
                    for (int na = 0; na < 4; ++na)
                        ubv[na] = *(const uint2*)(fB + (wnl + na * 8 + r) * 64 + coff);
#pragma unroll
                    for (int ma = 0; ma < 4; ++ma)
#pragma unroll
                        for (int na = 0; na < 4; ++na)
                            mma16816(cf1[ma][na], ua[ma].x, ub_[ma].x, ua[ma].y, ub_[ma].y,
                                     ubv[na].x, ubv[na].y);
                }
                __syncthreads();
                if (s + 2 < 4) { cpB1(np, s + 2); cp_commit(); }
            }
#pragma unroll
            for (int ma = 0; ma < 4; ++ma) {
                const int row0 = ma * 16 + r;
#pragma unroll
                for (int na = 0; na < 4; ++na) {
                    const int nloc = np * 256 + wnl + na * 8 + 2 * c;
                    stsC(sQ, row0,     nloc, cf1[ma][na][0], cf1[ma][na][1]);
                    stsC(sQ, row0 + 8, nloc, cf1[ma][na][2], cf1[ma][na][3]);
                }
            }
            __syncthreads();
        }
    }

    // ================= Phase 2: W2 + W3 =================
    {
        float* sB2 = (float*)sEf;            // 256 f32
        float* sW3 = (float*)(sEf + 1024);   // 256 f32
        float* psum = (float*)(sEf + 2048);  // 64 x 8 f32
        sB2[tid] = __ldg(b2 + tid);
        sW3[tid] = __ldg(W3 + tid);

        const int row = tid >> 2, j = tid & 3;
        const int e = min(bm + row, M - 1);
        const __half* paP = g_pab + (size_t)g_src[e] * 1024;
        const __half* pbP = g_pab + (size_t)g_dst[e] * 1024 + 512;
        char* qaddrBase = sQ + row * 64 + ((j ^ (row & 3)) << 4);

        uint4 ra, rb;
        auto ldgA = [&](int s) {
            ra = __ldg((const uint4*)(paP + s * 32 + j * 8));
            rb = __ldg((const uint4*)(pbP + s * 32 + j * 8));
        };
        auto finA = [&](int s) {
            uint4 q4 = *(uint4*)(qaddrBase + s * 4096);
            const half2* qh = (const half2*)&q4;
            const half2* ha = (const half2*)&ra;
            const half2* hb = (const half2*)&rb;
            half2 v[4];
            const half2 z = __float2half2_rn(0.f);
#pragma unroll
            for (int i = 0; i < 4; ++i)
                v[i] = __hmax2(__hadd2(__hadd2(qh[i], ha[i]), hb[i]), z);
            *(uint4*)(qaddrBase + s * 4096) = *(uint4*)v;
        };
        auto cpB2 = [&](int s) {
            char* dB = sStr + (s & 1) * 16384;
#pragma unroll
            for (int t = 0; t < 4; ++t) {
                int idx = tid + t * 256;
                int n = idx >> 2, j2 = idx & 3;
                cp_async16(dB + n * 64 + ((j2 ^ (n & 3)) << 4),
                           g_w2t + (size_t)n * 512 + s * 32 + j2 * 8);
            }
        };

        const int wnl = warp * 32;
        float cf[4][4][4] = {};

        ldgA(0);
        cpB2(0); cp_commit();
        cpB2(1); cp_commit();

#pragma unroll 1
        for (int s = 0; s < 16; ++s) {
            finA(s);
            if (s + 1 < 16) ldgA(s + 1);
            if (s + 1 < 16) cp_wait1(); else cp_wait0();
            __syncthreads();
            const char* fA = sQ + s * 4096;
            const char* fB = sStr + (s & 1) * 16384;
#pragma unroll
            for (int g = 0; g < 2; ++g) {
                const int coff = (((g * 2 + (c >> 1)) ^ (r & 3)) << 4) + (c & 1) * 8;
                uint2 ua[4], ub_[4], ubv[4];
#pragma unroll
                for (int ma = 0; ma < 4; ++ma) {
                    const int row0 = ma * 16 + r;
                    ua[ma]  = *(const uint2*)(fA + row0 * 64 + coff);
                    ub_[ma] = *(const uint2*)(fA + (row0 + 8) * 64 + coff);
                }
#pragma unroll
                for (int na = 0; na < 4; ++na)
                    ubv[na] = *(const uint2*)(fB + (wnl + na * 8 + r) * 64 + coff);
#pragma unroll
                for (int ma = 0; ma < 4; ++ma)
#pragma unroll
                    for (int na = 0; na < 4; ++na)
                        mma16816(cf[ma][na], ua[ma].x, ub_[ma].x, ua[ma].y, ub_[ma].y,
                                 ubv[na].x, ubv[na].y);
            }
            __syncthreads();
            if (s + 2 < 16) { cpB2(s + 2); cp_commit(); }
        }

        float2 bias2[4], w3v[4];
#pragma unroll
        for (int na = 0; na < 4; ++na) {
            bias2[na] = *(const float2*)&sB2[wnl + na * 8 + 2 * c];
            w3v[na]   = *(const float2*)&sW3[wnl + na * 8 + 2 * c];
        }
#pragma unroll
        for (int ma = 0; ma < 4; ++ma) {
            float p0 = 0.f, p1 = 0.f;
#pragma unroll
            for (int na = 0; na < 4; ++na) {
                p0 += fmaxf(cf[ma][na][0] + bias2[na].x, 0.f) * w3v[na].x
                    + fmaxf(cf[ma][na][1] + bias2[na].y, 0.f) * w3v[na].y;
                p1 += fmaxf(cf[ma][na][2] + bias2[na].x, 0.f) * w3v[na].x
                    + fmaxf(cf[ma][na][3] + bias2[na].y, 0.f) * w3v[na].y;
            }
            p0 += __shfl_xor_sync(0xffffffffu, p0, 1);
            p0 += __shfl_xor_sync(0xffffffffu, p0, 2);
            p1 += __shfl_xor_sync(0xffffffffu, p1, 1);
            p1 += __shfl_xor_sync(0xffffffffu, p1, 2);
            if (c == 0) {
                const int rl = ma * 16 + r;
                psum[rl * 8 + warp] = p0;
                psum[(rl + 8) * 8 + warp] = p1;
            }
        }
        __syncthreads();
        if (tid < 64) {
            const int gm = bm + tid;
            if (gm < M) {
                float s = 0.f;
#pragma unroll
                for (int w = 0; w < 8; ++w) s += psum[tid * 8 + w];
                outv[gm] = s + __ldg(b3);
            }
        }
    }
}

// ============================================================================
extern "C" void kernel_launch(void* const* d_in, const int* in_sizes, int n_in,
                              void* d_out, int out_size)
{
    const float* x     = (const float*)d_in[0];
    const void*  eidx  = d_in[1];
    const float* eattr = (const float*)d_in[2];
    const float* Wn    = (const float*)d_in[3];
    const float* bnode = (const float*)d_in[4];
    const float* We    = (const float*)d_in[5];
    const float* be    = (const float*)d_in[6];
    const float* W1    = (const float*)d_in[7];
    const float* b1    = (const float*)d_in[8];
    const float* W2    = (const float*)d_in[9];
    const float* b2    = (const float*)d_in[10];
    const float* W3    = (const float*)d_in[11];
    const float* b3    = (const float*)d_in[12];
    float* out = (float*)d_out;

    __half *p_node, *p_pab, *p_xt, *p_wnt, *p_w1ab;
    float* p_b1024;
    cudaGetSymbolAddress((void**)&p_node, g_node_f);
    cudaGetSymbolAddress((void**)&p_pab, g_pab);
    cudaGetSymbolAddress((void**)&p_xt, g_xt);
    cudaGetSymbolAddress((void**)&p_wnt, g_wnt);
    cudaGetSymbolAddress((void**)&p_w1ab, g_w1ab);
    cudaGetSymbolAddress((void**)&p_b1024, g_bias1024);

    // launches: 0 detect, 1 conv, 2 prep, 3 node_enc, 4 pab, 5 fq
    detect_idx_kernel<<<1, 32>>>(eidx);
    conv_idx_kernel<<<(kEdges + 255) / 256, 256>>>(eidx);
    prep_kernel<<<13880, 256>>>(x, Wn, We, W1, W2, b1);

    // node encoder [50000,128]
    cudaFuncSetAttribute(mm_kernel<128, 128, true>,
                         cudaFuncAttributeMaxDynamicSharedMemorySize, MM_SMEM);
    mm_kernel<128, 128, true><<<dim3(1, (kNodes + 127) / 128), 256, MM_SMEM>>>(
        p_xt, p_wnt, bnode, p_node, kNodes);

    // Pab = node_f @ [W1a|W1b] + [b1|0]   [50000,1024]
    cudaFuncSetAttribute(mm_kernel<128, 1024, false>,
                         cudaFuncAttributeMaxDynamicSharedMemorySize, MM_SMEM);
    mm_kernel<128, 1024, false><<<dim3(8, (kNodes + 127) / 128), 256, MM_SMEM>>>(
        p_node, p_w1ab, p_b1024, p_pab, kNodes);

    // fused edge pipeline
    cudaFuncSetAttribute(fq_kernel,
                         cudaFuncAttributeMaxDynamicSharedMemorySize, FQ_SMEM);
    fq_kernel<<<(kEdges + 63) / 64, 256, FQ_SMEM>>>(eattr, be, b2, W3, b3, out, kEdges);
}